// round 2
// baseline (speedup 1.0000x reference)
#include <cuda_runtime.h>
#include <cuda_bf16.h>

// Problem shapes (fixed by the dataset)
#define N_SEQ   256
#define M_GENES 2000
#define D_DIM   128
#define N_NUC   4
#define TABLE_ROWS (M_GENES * N_NUC)          // 8000
#define TABLE_ELEMS (TABLE_ROWS * D_DIM)      // 1,024,000 floats = 4 MB

// Scratch for the normalized table (no cudaMalloc allowed)
__device__ float g_table[TABLE_ELEMS];

// Kernel 1: normalize each (gene, nucleotide) row of the embedding table.
// One warp per 128-float row: float4 load, warp-reduce sum of squares, scale.
__global__ void normalize_kernel(const float* __restrict__ emb) {
    int warp = (blockIdx.x * blockDim.x + threadIdx.x) >> 5;
    int lane = threadIdx.x & 31;
    if (warp >= TABLE_ROWS) return;

    const float4* src = reinterpret_cast<const float4*>(emb + (size_t)warp * D_DIM);
    float4 v = src[lane];
    float ss = v.x * v.x + v.y * v.y + v.z * v.z + v.w * v.w;
    #pragma unroll
    for (int o = 16; o > 0; o >>= 1)
        ss += __shfl_xor_sync(0xffffffffu, ss, o);

    float inv = 1.0f / fmaxf(sqrtf(ss), 1e-12f);
    v.x *= inv; v.y *= inv; v.z *= inv; v.w *= inv;
    reinterpret_cast<float4*>(g_table + (size_t)warp * D_DIM)[lane] = v;
}

// Kernel 2: gather. One warp per output row (n, m); each lane copies one float4.
// out[n][m][:] = g_table[(m*4 + gene_seq[n][m])][:]
__global__ void gather_kernel(const int* __restrict__ seq,
                              float* __restrict__ out) {
    unsigned long long tid =
        (unsigned long long)blockIdx.x * blockDim.x + threadIdx.x;
    unsigned int lane = threadIdx.x & 31u;
    unsigned long long row = tid >> 5;               // n * M_GENES + m
    unsigned int m = (unsigned int)(row % M_GENES);

    int g = __ldg(seq + row);                        // warp-uniform broadcast
    const float4* src = reinterpret_cast<const float4*>(
        g_table + ((size_t)(m * N_NUC + g)) * D_DIM);

    reinterpret_cast<float4*>(out)[tid] = src[lane];
}

extern "C" void kernel_launch(void* const* d_in, const int* in_sizes, int n_in,
                              void* d_out, int out_size) {
    const int*   gene_seq = (const int*)d_in[0];     // (256, 2000) int32
    const float* emb      = (const float*)d_in[1];   // (2000, 4, 128) f32
    float*       out      = (float*)d_out;           // (256, 2000, 128) f32

    // Kernel 1: 8000 warps -> 8000*32 threads / 256 = 1000 blocks
    normalize_kernel<<<(TABLE_ROWS * 32 + 255) / 256, 256>>>(emb);

    // Kernel 2: 256*2000 rows * 32 lanes = 16,384,000 threads
    unsigned long long total = (unsigned long long)N_SEQ * M_GENES * 32ull;
    gather_kernel<<<(unsigned int)(total / 256ull), 256>>>(gene_seq, out);
}

// round 3
// speedup vs baseline: 1.5479x; 1.5479x over previous
#include <cuda_runtime.h>
#include <cuda_bf16.h>

#define N_SEQ   256
#define M_GENES 2000
#define D_DIM   128
#define N_NUC   4
#define TABLE_ROWS (M_GENES * N_NUC)          // 8000
#define TABLE_ELEMS (TABLE_ROWS * D_DIM)      // 4 MB
#define ROWS_PER_WARP 8
#define TOTAL_ROWS (N_SEQ * M_GENES)          // 512000

// Scratch for the normalized table (no cudaMalloc allowed)
__device__ float g_table[TABLE_ELEMS];

// Kernel 1: normalize each (gene, nucleotide) row. One warp per 128-float row.
__global__ void normalize_kernel(const float* __restrict__ emb) {
    int warp = (blockIdx.x * blockDim.x + threadIdx.x) >> 5;
    int lane = threadIdx.x & 31;
    if (warp >= TABLE_ROWS) return;

    const float4* src = reinterpret_cast<const float4*>(emb + (size_t)warp * D_DIM);
    float4 v = src[lane];
    float ss = v.x * v.x + v.y * v.y + v.z * v.z + v.w * v.w;
    #pragma unroll
    for (int o = 16; o > 0; o >>= 1)
        ss += __shfl_xor_sync(0xffffffffu, ss, o);

    float inv = 1.0f / fmaxf(sqrtf(ss), 1e-12f);
    v.x *= inv; v.y *= inv; v.z *= inv; v.w *= inv;
    reinterpret_cast<float4*>(g_table + (size_t)warp * D_DIM)[lane] = v;
}

// Kernel 2: gather, 8 rows per warp for MLP.
// out[n][m][:] = g_table[(m*4 + gene_seq[n][m])][:]
__global__ void __launch_bounds__(256) gather_kernel(const int* __restrict__ seq,
                                                     float* __restrict__ out) {
    unsigned int warp = (blockIdx.x * blockDim.x + threadIdx.x) >> 5;
    unsigned int lane = threadIdx.x & 31u;
    unsigned int row0 = warp * ROWS_PER_WARP;

    // lanes 0..7 load the 8 indices in one coalesced access
    int g = 0;
    if (lane < ROWS_PER_WARP) g = __ldg(seq + row0 + lane);

    unsigned int m0 = row0 % M_GENES;   // consecutive rows may wrap the n boundary

    // Issue 8 independent table loads back-to-back (MLP=8)
    float4 v[ROWS_PER_WARP];
    #pragma unroll
    for (int r = 0; r < ROWS_PER_WARP; r++) {
        int gr = __shfl_sync(0xffffffffu, g, r);
        unsigned int m = m0 + r;
        if (m >= M_GENES) m -= M_GENES;
        const float4* src = reinterpret_cast<const float4*>(
            g_table + ((size_t)(m * N_NUC + gr)) * D_DIM);
        v[r] = src[lane];
    }

    // 8 streaming stores: 4 KB contiguous per warp, output never re-read
    float4* dst = reinterpret_cast<float4*>(out) + (size_t)row0 * 32 + lane;
    #pragma unroll
    for (int r = 0; r < ROWS_PER_WARP; r++) {
        __stcs(dst + (size_t)r * 32, v[r]);
    }
}

extern "C" void kernel_launch(void* const* d_in, const int* in_sizes, int n_in,
                              void* d_out, int out_size) {
    const int*   gene_seq = (const int*)d_in[0];     // (256, 2000) int32
    const float* emb      = (const float*)d_in[1];   // (2000, 4, 128) f32
    float*       out      = (float*)d_out;           // (256, 2000, 128) f32

    normalize_kernel<<<(TABLE_ROWS * 32 + 255) / 256, 256>>>(emb);

    // 512000 rows / 8 rows-per-warp = 64000 warps; 8 warps per 256-thread block
    unsigned int nwarps = TOTAL_ROWS / ROWS_PER_WARP;
    gather_kernel<<<nwarps / 8, 256>>>(gene_seq, out);
}